// round 6
// baseline (speedup 1.0000x reference)
#include <cuda_runtime.h>

typedef unsigned long long ull;

__device__ __forceinline__ ull pack2(float a, float b) {
    ull r;
    asm("mov.b64 %0, {%1, %2};" : "=l"(r) : "f"(a), "f"(b));
    return r;
}
__device__ __forceinline__ void unpack2(ull v, float& a, float& b) {
    asm("mov.b64 {%0, %1}, %2;" : "=f"(a), "=f"(b) : "l"(v));
}
__device__ __forceinline__ void ffma2(ull& d, ull a, ull b) {
    asm("fma.rn.f32x2 %0, %1, %2, %0;" : "+l"(d) : "l"(a), "l"(b));
}

#define NTILES 1024
#define NBLOCKS 296

// ---------------------------------------------------------------------------
// Persistent fused kernel.
// Prologue (once per block, 296 blocks = 2/SM): build the 16x16
// StronglyEntanglingLayers unitary from weights (2,4,3) into sW.
// Then grid-stride over 1024 (batch, 8-row strip) tiles; per tile each thread
// computes a 4(x) x 2(y) pixel quad for all 16 channels with (re,im)-packed
// f32x2 accumulators.
// out[b][ch][y][x] = min(8 * |U_ch . p|^2 / ||p||^2, 1)
// ---------------------------------------------------------------------------
__global__ __launch_bounds__(256, 2)
void qconv_kernel(const float* __restrict__ x, const float* __restrict__ w,
                  float* __restrict__ out) {
    __shared__ ull sW[144];
    __shared__ float2 gates[8][4];
    __shared__ float2 cur[16][16];
    __shared__ float2 Lm[16][16];
    __shared__ float2 tmp[16][16];

    const int tid = threadIdx.y * 64 + threadIdx.x;

    // ---------------- Prologue: build unitary (once per block) -------------
    {
        int i = tid >> 4, j = tid & 15;

        if (tid < 32) {
            int g = tid >> 2, e = tid & 3;
            int bi = e >> 1, bj = e & 1;
            float phi = w[g * 3 + 0];
            float th  = w[g * 3 + 1];
            float om  = w[g * 3 + 2];
            float sh, chf;
            __sincosf(0.5f * th, &sh, &chf);
            float mag, phs;
            if (!bi && !bj)      { mag =  chf; phs = -0.5f * (phi + om); }
            else if (!bi &&  bj) { mag = -sh;  phs =  0.5f * (phi - om); }
            else if ( bi && !bj) { mag =  sh;  phs = -0.5f * (phi - om); }
            else                 { mag =  chf; phs =  0.5f * (phi + om); }
            float sp, cp;
            __sincosf(phs, &sp, &cp);
            gates[g][e] = make_float2(mag * cp, mag * sp);
        }
        cur[i][j] = make_float2(i == j ? 1.f : 0.f, 0.f);
        __syncthreads();

#pragma unroll 1
        for (int l = 0; l < 2; l++) {
            float2 vv = make_float2(1.f, 0.f);
#pragma unroll
            for (int wi = 0; wi < 4; wi++) {
                int bi = (i >> (3 - wi)) & 1;
                int bj = (j >> (3 - wi)) & 1;
                float2 e = gates[l * 4 + wi][bi * 2 + bj];
                vv = make_float2(vv.x * e.x - vv.y * e.y, vv.x * e.y + vv.y * e.x);
            }
            Lm[i][j] = vv;
            __syncthreads();

            float2 acc = make_float2(0.f, 0.f);
#pragma unroll
            for (int k = 0; k < 16; k++) {
                float2 a = Lm[i][k], bb = cur[k][j];
                acc.x += a.x * bb.x - a.y * bb.y;
                acc.y += a.x * bb.y + a.y * bb.x;
            }
            tmp[i][j] = acc;
            __syncthreads();

            int r = (l % 3) + 1;
            int q = i;
#pragma unroll
            for (int m = 3; m >= 0; m--) {
                int tt = (m + r) & 3;
                int cb = 1 << (3 - m), tb = 1 << (3 - tt);
                if (q & cb) q ^= tb;
            }
            cur[i][j] = tmp[q][j];
            __syncthreads();
        }

        if (j < 9) {
            float2 u = cur[i][j];
            sW[i * 9 + j] = pack2(u.x, u.y);
        }
        __syncthreads();
    }

    // ---------------- Grid-stride tile loop ----------------
    const int x0 = threadIdx.x * 4;                           // 0..252

#pragma unroll 1
    for (int t = blockIdx.x; t < NTILES; t += NBLOCKS) {
        const int b     = t >> 5;
        const int strip = t & 31;
        const int r0 = strip * 8 + threadIdx.y * 2;           // 0..254

        const float* xin = x + (size_t)b * 65536;

        // Load 4 rows (r0-1 .. r0+2) x 6 cols (x0-1 .. x0+4), pad = 0.01
        float v[4][6];
#pragma unroll
        for (int i = 0; i < 4; i++) {
            int ry = r0 - 1 + i;
            if (ry >= 0 && ry < 256) {
                const float* rp = xin + ry * 256;
                float4 q = *(const float4*)(rp + x0);
                v[i][1] = q.x; v[i][2] = q.y; v[i][3] = q.z; v[i][4] = q.w;
                v[i][0] = (x0 > 0)   ? rp[x0 - 1] : 0.01f;
                v[i][5] = (x0 < 252) ? rp[x0 + 4] : 0.01f;
            } else {
#pragma unroll
                for (int c = 0; c < 6; c++) v[i][c] = 0.01f;
            }
        }

        // ||p||^2 per pixel via separable row sums, then 8/s (guarded)
        float h[4][4];
#pragma unroll
        for (int i = 0; i < 4; i++) {
            float sq[6];
#pragma unroll
            for (int c = 0; c < 6; c++) sq[c] = v[i][c] * v[i][c];
#pragma unroll
            for (int c = 0; c < 4; c++) h[i][c] = sq[c] + sq[c + 1] + sq[c + 2];
        }
        float inv[2][4];
#pragma unroll
        for (int r = 0; r < 2; r++)
#pragma unroll
            for (int c = 0; c < 4; c++) {
                float s = h[r][c] + h[r + 1][c] + h[r + 2][c];
                inv[r][c] = (s > 1e-24f) ? __fdividef(8.0f, s) : 0.0f;
            }

        // Broadcast-packed patch values for f32x2 FMAs
        ull pp[4][6];
#pragma unroll
        for (int i = 0; i < 4; i++)
#pragma unroll
            for (int c = 0; c < 6; c++) pp[i][c] = pack2(v[i][c], v[i][c]);

        float* ob = out + (size_t)b * 16 * 65536 + (size_t)r0 * 256 + x0;

#pragma unroll 1
        for (int ch = 0; ch < 16; ch++) {
            ull C[9];
#pragma unroll
            for (int k = 0; k < 9; k++) C[k] = sW[ch * 9 + k];

            ull acc[2][4];
#pragma unroll
            for (int r = 0; r < 2; r++)
#pragma unroll
                for (int c = 0; c < 4; c++) acc[r][c] = 0ULL;

#pragma unroll
            for (int dr = 0; dr < 3; dr++)
#pragma unroll
                for (int dc = 0; dc < 3; dc++) {
                    ull cf = C[dr * 3 + dc];
#pragma unroll
                    for (int r = 0; r < 2; r++)
#pragma unroll
                        for (int c = 0; c < 4; c++)
                            ffma2(acc[r][c], cf, pp[r + dr][c + dc]);
                }

#pragma unroll
            for (int r = 0; r < 2; r++) {
                float res[4];
#pragma unroll
                for (int c = 0; c < 4; c++) {
                    float re, im;
                    unpack2(acc[r][c], re, im);
                    float mag = re * re + im * im;
                    res[c] = fminf(mag * inv[r][c], 1.0f);
                }
                *(float4*)(ob + (size_t)ch * 65536 + (size_t)r * 256) =
                    make_float4(res[0], res[1], res[2], res[3]);
            }
        }
    }
}

extern "C" void kernel_launch(void* const* d_in, const int* in_sizes, int n_in,
                              void* d_out, int out_size) {
    const float* x = (const float*)d_in[0];        // (32,1,256,256) fp32
    const float* w = (const float*)d_in[1];        // (2,4,3) fp32
    float* out = (float*)d_out;                    // (32,16,256,256) fp32

    dim3 block(64, 4, 1);
    dim3 grid(NBLOCKS, 1, 1);
    qconv_kernel<<<grid, block>>>(x, w, out);
}

// round 8
// speedup vs baseline: 1.0662x; 1.0662x over previous
#include <cuda_runtime.h>

typedef unsigned long long ull;

__device__ __forceinline__ ull pack2(float a, float b) {
    ull r;
    asm("mov.b64 %0, {%1, %2};" : "=l"(r) : "f"(a), "f"(b));
    return r;
}
__device__ __forceinline__ void unpack2(ull v, float& a, float& b) {
    asm("mov.b64 {%0, %1}, %2;" : "=f"(a), "=f"(b) : "l"(v));
}
__device__ __forceinline__ void ffma2(ull& d, ull a, ull b) {
    asm("fma.rn.f32x2 %0, %1, %2, %0;" : "+l"(d) : "l"(a), "l"(b));
}

// CNOT-ring row permutation for layer with range r: dest row i <- src row q
__device__ __forceinline__ int cnot_perm(int i, int r) {
    int q = i;
#pragma unroll
    for (int m = 3; m >= 0; m--) {
        int tt = (m + r) & 3;
        int cb = 1 << (3 - m), tb = 1 << (3 - tt);
        if (q & cb) q ^= tb;
    }
    return q;
}

// ---------------------------------------------------------------------------
// Fused kernel, fast prologue.
// U[i][j] = sum_k L2[q2(i)][k] * L1[q1(k)][j]   (q1: r=1, q2: r=2)
// L1/L2 kron elements built per-thread from 8 shared 2x2 gates.
// Then: each thread computes a 4(x) x 2(y) pixel quad, all 16 channels,
// (re,im)-packed f32x2 accumulators (R1 mainloop).
// out[b][ch][y][x] = min(8 * |U_ch . p|^2 / ||p||^2, 1)
// ---------------------------------------------------------------------------
__global__ __launch_bounds__(256, 2)
void qconv_kernel(const float* __restrict__ x, const float* __restrict__ w,
                  float* __restrict__ out) {
    __shared__ ull sW[144];
    __shared__ float2 gates[8][4];
    __shared__ float2 sL1[16][16];
    __shared__ float2 sL2[16][16];

    const int tid = threadIdx.y * 64 + threadIdx.x;
    {
        const int i = tid >> 4, j = tid & 15;

        // Stage 1: 8 single-qubit Rot gates (warp 0)
        if (tid < 32) {
            int g = tid >> 2, e = tid & 3;
            int bi = e >> 1, bj = e & 1;
            float phi = w[g * 3 + 0];
            float th  = w[g * 3 + 1];
            float om  = w[g * 3 + 2];
            float sh, chf;
            __sincosf(0.5f * th, &sh, &chf);
            float mag, phs;
            if (!bi && !bj)      { mag =  chf; phs = -0.5f * (phi + om); }
            else if (!bi &&  bj) { mag = -sh;  phs =  0.5f * (phi - om); }
            else if ( bi && !bj) { mag =  sh;  phs = -0.5f * (phi - om); }
            else                 { mag =  chf; phs =  0.5f * (phi + om); }
            float sp, cp;
            __sincosf(phs, &sp, &cp);
            gates[g][e] = make_float2(mag * cp, mag * sp);
        }
        __syncthreads();

        // Stage 2: kron elements of both layer matrices (one (i,j) per thread)
        {
            float2 v1 = make_float2(1.f, 0.f);
            float2 v2 = make_float2(1.f, 0.f);
#pragma unroll
            for (int wi = 0; wi < 4; wi++) {
                int bi = (i >> (3 - wi)) & 1;
                int bj = (j >> (3 - wi)) & 1;
                float2 e1 = gates[wi][bi * 2 + bj];
                float2 e2 = gates[4 + wi][bi * 2 + bj];
                v1 = make_float2(v1.x * e1.x - v1.y * e1.y, v1.x * e1.y + v1.y * e1.x);
                v2 = make_float2(v2.x * e2.x - v2.y * e2.y, v2.x * e2.y + v2.y * e2.x);
            }
            sL1[i][j] = v1;
            sL2[i][j] = v2;
        }
        __syncthreads();

        // Stage 3: U[i][j] = sum_k L2[q2(i)][k] * L1[q1(k)][j], j<9
        if (j < 9) {
            const int iq = cnot_perm(i, 2);
            float2 acc = make_float2(0.f, 0.f);
#pragma unroll
            for (int k = 0; k < 16; k++) {
                const int kq = cnot_perm(k, 1);   // compile-time constant
                float2 a = sL2[iq][k];
                float2 bb = sL1[kq][j];
                acc.x += a.x * bb.x - a.y * bb.y;
                acc.y += a.x * bb.y + a.y * bb.x;
            }
            sW[i * 9 + j] = pack2(acc.x, acc.y);
        }
        __syncthreads();
    }

    // ---------------- Conv (R1 mainloop) ----------------
    const int b  = blockIdx.z;
    const int x0 = threadIdx.x * 4;                       // 0..252
    const int r0 = blockIdx.y * 8 + threadIdx.y * 2;      // 0..254

    const float* xin = x + (size_t)b * 65536;

    // Load 4 rows (r0-1 .. r0+2) x 6 cols (x0-1 .. x0+4), pad = 0.01
    float v[4][6];
#pragma unroll
    for (int i = 0; i < 4; i++) {
        int ry = r0 - 1 + i;
        if (ry >= 0 && ry < 256) {
            const float* rp = xin + ry * 256;
            float4 q = *(const float4*)(rp + x0);
            v[i][1] = q.x; v[i][2] = q.y; v[i][3] = q.z; v[i][4] = q.w;
            v[i][0] = (x0 > 0)   ? rp[x0 - 1] : 0.01f;
            v[i][5] = (x0 < 252) ? rp[x0 + 4] : 0.01f;
        } else {
#pragma unroll
            for (int c = 0; c < 6; c++) v[i][c] = 0.01f;
        }
    }

    // ||p||^2 per pixel via separable row sums, then 8/s (guarded)
    float h[4][4];
#pragma unroll
    for (int i = 0; i < 4; i++) {
        float sq[6];
#pragma unroll
        for (int c = 0; c < 6; c++) sq[c] = v[i][c] * v[i][c];
#pragma unroll
        for (int c = 0; c < 4; c++) h[i][c] = sq[c] + sq[c + 1] + sq[c + 2];
    }
    float inv[2][4];
#pragma unroll
    for (int r = 0; r < 2; r++)
#pragma unroll
        for (int c = 0; c < 4; c++) {
            float s = h[r][c] + h[r + 1][c] + h[r + 2][c];
            inv[r][c] = (s > 1e-24f) ? __fdividef(8.0f, s) : 0.0f;
        }

    // Broadcast-packed patch values for f32x2 FMAs
    ull pp[4][6];
#pragma unroll
    for (int i = 0; i < 4; i++)
#pragma unroll
        for (int c = 0; c < 6; c++) pp[i][c] = pack2(v[i][c], v[i][c]);

    float* ob = out + (size_t)b * 16 * 65536 + (size_t)r0 * 256 + x0;

#pragma unroll 1
    for (int ch = 0; ch < 16; ch++) {
        ull C[9];
#pragma unroll
        for (int k = 0; k < 9; k++) C[k] = sW[ch * 9 + k];

        ull acc[2][4];
#pragma unroll
        for (int r = 0; r < 2; r++)
#pragma unroll
            for (int c = 0; c < 4; c++) acc[r][c] = 0ULL;

#pragma unroll
        for (int dr = 0; dr < 3; dr++)
#pragma unroll
            for (int dc = 0; dc < 3; dc++) {
                ull cf = C[dr * 3 + dc];
#pragma unroll
                for (int r = 0; r < 2; r++)
#pragma unroll
                    for (int c = 0; c < 4; c++)
                        ffma2(acc[r][c], cf, pp[r + dr][c + dc]);
            }

#pragma unroll
        for (int r = 0; r < 2; r++) {
            float res[4];
#pragma unroll
            for (int c = 0; c < 4; c++) {
                float re, im;
                unpack2(acc[r][c], re, im);
                float mag = re * re + im * im;
                res[c] = fminf(mag * inv[r][c], 1.0f);
            }
            *(float4*)(ob + (size_t)ch * 65536 + (size_t)r * 256) =
                make_float4(res[0], res[1], res[2], res[3]);
        }
    }
}

extern "C" void kernel_launch(void* const* d_in, const int* in_sizes, int n_in,
                              void* d_out, int out_size) {
    const float* x = (const float*)d_in[0];        // (32,1,256,256) fp32
    const float* w = (const float*)d_in[1];        // (2,4,3) fp32
    float* out = (float*)d_out;                    // (32,16,256,256) fp32

    dim3 block(64, 4, 1);
    dim3 grid(1, 32, 32);
    qconv_kernel<<<grid, block>>>(x, w, out);
}

// round 9
// speedup vs baseline: 1.0926x; 1.0248x over previous
#include <cuda_runtime.h>

typedef unsigned long long ull;

__device__ __forceinline__ ull pack2(float a, float b) {
    ull r;
    asm("mov.b64 %0, {%1, %2};" : "=l"(r) : "f"(a), "f"(b));
    return r;
}
__device__ __forceinline__ void unpack2(ull v, float& a, float& b) {
    asm("mov.b64 {%0, %1}, %2;" : "=f"(a), "=f"(b) : "l"(v));
}
__device__ __forceinline__ void ffma2(ull& d, ull a, ull b) {
    asm("fma.rn.f32x2 %0, %1, %2, %0;" : "+l"(d) : "l"(a), "l"(b));
}

// CNOT-ring row permutation for layer with range r: dest row i <- src row q
__device__ __forceinline__ int cnot_perm(int i, int r) {
    int q = i;
#pragma unroll
    for (int m = 3; m >= 0; m--) {
        int tt = (m + r) & 3;
        int cb = 1 << (3 - m), tb = 1 << (3 - tt);
        if (q & cb) q ^= tb;
    }
    return q;
}

// ---------------------------------------------------------------------------
// Fused kernel, overlapped prologue.
// Order: (1) issue conv-input LDGs; (2) build U in smem (gates -> kron ->
// permuted dot), overlapping the input DRAM latency; (3) consume inputs into
// norm + packed patch regs before the final barrier; (4) R1 mainloop.
// out[b][ch][y][x] = min(8 * |U_ch . p|^2 / ||p||^2, 1)
// ---------------------------------------------------------------------------
__global__ __launch_bounds__(256, 2)
void qconv_kernel(const float* __restrict__ x, const float* __restrict__ w,
                  float* __restrict__ out) {
    __shared__ ull sW[144];
    __shared__ float2 gates[8][4];
    __shared__ float2 sL1[16][16];
    __shared__ float2 sL2[16][16];

    const int tid = threadIdx.y * 64 + threadIdx.x;
    const int b  = blockIdx.z;
    const int x0 = threadIdx.x * 4;                       // 0..252
    const int r0 = blockIdx.y * 8 + threadIdx.y * 2;      // 0..254
    const float* xin = x + (size_t)b * 65536;

    // ---- (1) Issue input loads first: 4 rows x 6 cols, pad = 0.01 ----
    float v[4][6];
#pragma unroll
    for (int i = 0; i < 4; i++) {
        int ry = r0 - 1 + i;
        if (ry >= 0 && ry < 256) {
            const float* rp = xin + ry * 256;
            float4 q = *(const float4*)(rp + x0);
            v[i][1] = q.x; v[i][2] = q.y; v[i][3] = q.z; v[i][4] = q.w;
            v[i][0] = (x0 > 0)   ? rp[x0 - 1] : 0.01f;
            v[i][5] = (x0 < 252) ? rp[x0 + 4] : 0.01f;
        } else {
#pragma unroll
            for (int c = 0; c < 6; c++) v[i][c] = 0.01f;
        }
    }

    // ---- (2) Build unitary (overlaps input latency) ----
    {
        const int i = tid >> 4, j = tid & 15;

        if (tid < 32) {
            int g = tid >> 2, e = tid & 3;
            int bi = e >> 1, bj = e & 1;
            float phi = w[g * 3 + 0];
            float th  = w[g * 3 + 1];
            float om  = w[g * 3 + 2];
            float sh, chf;
            __sincosf(0.5f * th, &sh, &chf);
            float mag, phs;
            if (!bi && !bj)      { mag =  chf; phs = -0.5f * (phi + om); }
            else if (!bi &&  bj) { mag = -sh;  phs =  0.5f * (phi - om); }
            else if ( bi && !bj) { mag =  sh;  phs = -0.5f * (phi - om); }
            else                 { mag =  chf; phs =  0.5f * (phi + om); }
            float sp, cp;
            __sincosf(phs, &sp, &cp);
            gates[g][e] = make_float2(mag * cp, mag * sp);
        }
        __syncthreads();

        // kron elements of both layer matrices (one (i,j) per thread)
        {
            float2 v1 = make_float2(1.f, 0.f);
            float2 v2 = make_float2(1.f, 0.f);
#pragma unroll
            for (int wi = 0; wi < 4; wi++) {
                int bi = (i >> (3 - wi)) & 1;
                int bj = (j >> (3 - wi)) & 1;
                float2 e1 = gates[wi][bi * 2 + bj];
                float2 e2 = gates[4 + wi][bi * 2 + bj];
                v1 = make_float2(v1.x * e1.x - v1.y * e1.y, v1.x * e1.y + v1.y * e1.x);
                v2 = make_float2(v2.x * e2.x - v2.y * e2.y, v2.x * e2.y + v2.y * e2.x);
            }
            sL1[i][j] = v1;
            sL2[i][j] = v2;
        }
        __syncthreads();

        // U[i][j] = sum_k L2[q2(i)][k] * L1[q1(k)][j], j<9
        if (j < 9) {
            const int iq = cnot_perm(i, 2);
            float2 acc = make_float2(0.f, 0.f);
#pragma unroll
            for (int k = 0; k < 16; k++) {
                const int kq = cnot_perm(k, 1);   // compile-time constant
                float2 a = sL2[iq][k];
                float2 bb = sL1[kq][j];
                acc.x += a.x * bb.x - a.y * bb.y;
                acc.y += a.x * bb.y + a.y * bb.x;
            }
            sW[i * 9 + j] = pack2(acc.x, acc.y);
        }
    }

    // ---- (3) Consume inputs (now arrived) before the last barrier ----
    float inv[2][4];
    {
        float h[4][4];
#pragma unroll
        for (int i = 0; i < 4; i++) {
            float sq[6];
#pragma unroll
            for (int c = 0; c < 6; c++) sq[c] = v[i][c] * v[i][c];
#pragma unroll
            for (int c = 0; c < 4; c++) h[i][c] = sq[c] + sq[c + 1] + sq[c + 2];
        }
#pragma unroll
        for (int r = 0; r < 2; r++)
#pragma unroll
            for (int c = 0; c < 4; c++) {
                float s = h[r][c] + h[r + 1][c] + h[r + 2][c];
                inv[r][c] = (s > 1e-24f) ? __fdividef(8.0f, s) : 0.0f;
            }
    }
    ull pp[4][6];
#pragma unroll
    for (int i = 0; i < 4; i++)
#pragma unroll
        for (int c = 0; c < 6; c++) pp[i][c] = pack2(v[i][c], v[i][c]);

    __syncthreads();   // sW ready

    // ---- (4) Channel mainloop (R1) ----
    float* ob = out + (size_t)b * 16 * 65536 + (size_t)r0 * 256 + x0;

#pragma unroll 1
    for (int ch = 0; ch < 16; ch++) {
        ull C[9];
#pragma unroll
        for (int k = 0; k < 9; k++) C[k] = sW[ch * 9 + k];

        ull acc[2][4];
#pragma unroll
        for (int r = 0; r < 2; r++)
#pragma unroll
            for (int c = 0; c < 4; c++) acc[r][c] = 0ULL;

#pragma unroll
        for (int dr = 0; dr < 3; dr++)
#pragma unroll
            for (int dc = 0; dc < 3; dc++) {
                ull cf = C[dr * 3 + dc];
#pragma unroll
                for (int r = 0; r < 2; r++)
#pragma unroll
                    for (int c = 0; c < 4; c++)
                        ffma2(acc[r][c], cf, pp[r + dr][c + dc]);
            }

#pragma unroll
        for (int r = 0; r < 2; r++) {
            float res[4];
#pragma unroll
            for (int c = 0; c < 4; c++) {
                float re, im;
                unpack2(acc[r][c], re, im);
                float mag = re * re + im * im;
                res[c] = fminf(mag * inv[r][c], 1.0f);
            }
            *(float4*)(ob + (size_t)ch * 65536 + (size_t)r * 256) =
                make_float4(res[0], res[1], res[2], res[3]);
        }
    }
}

extern "C" void kernel_launch(void* const* d_in, const int* in_sizes, int n_in,
                              void* d_out, int out_size) {
    const float* x = (const float*)d_in[0];        // (32,1,256,256) fp32
    const float* w = (const float*)d_in[1];        // (2,4,3) fp32
    float* out = (float*)d_out;                    // (32,16,256,256) fp32

    dim3 block(64, 4, 1);
    dim3 grid(1, 32, 32);
    qconv_kernel<<<grid, block>>>(x, w, out);
}

// round 10
// speedup vs baseline: 1.1150x; 1.0205x over previous
#include <cuda_runtime.h>

typedef unsigned long long ull;

__device__ __forceinline__ ull pack2(float a, float b) {
    ull r;
    asm("mov.b64 %0, {%1, %2};" : "=l"(r) : "f"(a), "f"(b));
    return r;
}
__device__ __forceinline__ void unpack2(ull v, float& a, float& b) {
    asm("mov.b64 {%0, %1}, %2;" : "=f"(a), "=f"(b) : "l"(v));
}
__device__ __forceinline__ void ffma2(ull& d, ull a, ull b) {
    asm("fma.rn.f32x2 %0, %1, %2, %0;" : "+l"(d) : "l"(a), "l"(b));
}

// CNOT-ring row permutation for layer with range r: dest row i <- src row q
__device__ __forceinline__ int cnot_perm(int i, int r) {
    int q = i;
#pragma unroll
    for (int m = 3; m >= 0; m--) {
        int tt = (m + r) & 3;
        int cb = 1 << (3 - m), tb = 1 << (3 - tt);
        if (q & cb) q ^= tb;
    }
    return q;
}

// ---------------------------------------------------------------------------
// Fused kernel, overlapped prologue + paired-coefficient LDS.128 mainloop.
// sW layout: per channel 5 x ulonglong2 = taps (0,1),(2,3),(4,5),(6,7),(8,_).
// out[b][ch][y][x] = min(8 * |U_ch . p|^2 / ||p||^2, 1)
// ---------------------------------------------------------------------------
__global__ __launch_bounds__(256, 3)
void qconv_kernel(const float* __restrict__ x, const float* __restrict__ w,
                  float* __restrict__ out) {
    __shared__ __align__(16) ulonglong2 sW2[16][5];
    __shared__ float2 gates[8][4];
    __shared__ float2 sL1[16][16];
    __shared__ float2 sL2[16][16];

    const int tid = threadIdx.y * 64 + threadIdx.x;
    const int b  = blockIdx.z;
    const int x0 = threadIdx.x * 4;                       // 0..252
    const int r0 = blockIdx.y * 8 + threadIdx.y * 2;      // 0..254
    const float* xin = x + (size_t)b * 65536;

    // ---- (1) Issue input loads first: 4 rows x 6 cols, pad = 0.01 ----
    float v[4][6];
#pragma unroll
    for (int i = 0; i < 4; i++) {
        int ry = r0 - 1 + i;
        if (ry >= 0 && ry < 256) {
            const float* rp = xin + ry * 256;
            float4 q = *(const float4*)(rp + x0);
            v[i][1] = q.x; v[i][2] = q.y; v[i][3] = q.z; v[i][4] = q.w;
            v[i][0] = (x0 > 0)   ? rp[x0 - 1] : 0.01f;
            v[i][5] = (x0 < 252) ? rp[x0 + 4] : 0.01f;
        } else {
#pragma unroll
            for (int c = 0; c < 6; c++) v[i][c] = 0.01f;
        }
    }

    // ---- (2) Build unitary (overlaps input latency) ----
    {
        const int i = tid >> 4, j = tid & 15;

        if (tid < 32) {
            int g = tid >> 2, e = tid & 3;
            int bi = e >> 1, bj = e & 1;
            float phi = w[g * 3 + 0];
            float th  = w[g * 3 + 1];
            float om  = w[g * 3 + 2];
            float sh, chf;
            __sincosf(0.5f * th, &sh, &chf);
            float mag, phs;
            if (!bi && !bj)      { mag =  chf; phs = -0.5f * (phi + om); }
            else if (!bi &&  bj) { mag = -sh;  phs =  0.5f * (phi - om); }
            else if ( bi && !bj) { mag =  sh;  phs = -0.5f * (phi - om); }
            else                 { mag =  chf; phs =  0.5f * (phi + om); }
            float sp, cp;
            __sincosf(phs, &sp, &cp);
            gates[g][e] = make_float2(mag * cp, mag * sp);
        }
        __syncthreads();

        // kron elements of both layer matrices (one (i,j) per thread)
        {
            float2 v1 = make_float2(1.f, 0.f);
            float2 v2 = make_float2(1.f, 0.f);
#pragma unroll
            for (int wi = 0; wi < 4; wi++) {
                int bi = (i >> (3 - wi)) & 1;
                int bj = (j >> (3 - wi)) & 1;
                float2 e1 = gates[wi][bi * 2 + bj];
                float2 e2 = gates[4 + wi][bi * 2 + bj];
                v1 = make_float2(v1.x * e1.x - v1.y * e1.y, v1.x * e1.y + v1.y * e1.x);
                v2 = make_float2(v2.x * e2.x - v2.y * e2.y, v2.x * e2.y + v2.y * e2.x);
            }
            sL1[i][j] = v1;
            sL2[i][j] = v2;
        }
        __syncthreads();

        // U[i][j] = sum_k L2[q2(i)][k] * L1[q1(k)][j], j<9
        if (j < 9) {
            const int iq = cnot_perm(i, 2);
            float2 acc = make_float2(0.f, 0.f);
#pragma unroll
            for (int k = 0; k < 16; k++) {
                const int kq = cnot_perm(k, 1);   // compile-time constant
                float2 a = sL2[iq][k];
                float2 bb = sL1[kq][j];
                acc.x += a.x * bb.x - a.y * bb.y;
                acc.y += a.x * bb.y + a.y * bb.x;
            }
            // tap j of channel i -> ull slot i*10 + j (pairs for LDS.128)
            ((ull*)sW2)[i * 10 + j] = pack2(acc.x, acc.y);
        }
    }

    // ---- (3) Consume inputs (now arrived) before the last barrier ----
    float inv[2][4];
    {
        float h[4][4];
#pragma unroll
        for (int i = 0; i < 4; i++) {
            float sq[6];
#pragma unroll
            for (int c = 0; c < 6; c++) sq[c] = v[i][c] * v[i][c];
#pragma unroll
            for (int c = 0; c < 4; c++) h[i][c] = sq[c] + sq[c + 1] + sq[c + 2];
        }
#pragma unroll
        for (int r = 0; r < 2; r++)
#pragma unroll
            for (int c = 0; c < 4; c++) {
                float s = h[r][c] + h[r + 1][c] + h[r + 2][c];
                inv[r][c] = (s > 1e-24f) ? __fdividef(8.0f, s) : 0.0f;
            }
    }
    ull pp[4][6];
#pragma unroll
    for (int i = 0; i < 4; i++)
#pragma unroll
        for (int c = 0; c < 6; c++) pp[i][c] = pack2(v[i][c], v[i][c]);

    __syncthreads();   // sW2 ready

    // ---- (4) Channel mainloop ----
    float* ob = out + (size_t)b * 16 * 65536 + (size_t)r0 * 256 + x0;

#pragma unroll 1
    for (int ch = 0; ch < 16; ch++) {
        // 4 x LDS.128 + 1 x LDS.64 for the 9 taps
        ull C[9];
        {
            const ulonglong2* wch = &sW2[ch][0];
            ulonglong2 p0 = wch[0];
            ulonglong2 p1 = wch[1];
            ulonglong2 p2 = wch[2];
            ulonglong2 p3 = wch[3];
            C[0] = p0.x; C[1] = p0.y;
            C[2] = p1.x; C[3] = p1.y;
            C[4] = p2.x; C[5] = p2.y;
            C[6] = p3.x; C[7] = p3.y;
            C[8] = ((const ull*)wch)[8];
        }

        ull acc[2][4];
#pragma unroll
        for (int r = 0; r < 2; r++)
#pragma unroll
            for (int c = 0; c < 4; c++) acc[r][c] = 0ULL;

#pragma unroll
        for (int dr = 0; dr < 3; dr++)
#pragma unroll
            for (int dc = 0; dc < 3; dc++) {
                ull cf = C[dr * 3 + dc];
#pragma unroll
                for (int r = 0; r < 2; r++)
#pragma unroll
                    for (int c = 0; c < 4; c++)
                        ffma2(acc[r][c], cf, pp[r + dr][c + dc]);
            }

#pragma unroll
        for (int r = 0; r < 2; r++) {
            float res[4];
#pragma unroll
            for (int c = 0; c < 4; c++) {
                float re, im;
                unpack2(acc[r][c], re, im);
                float mag = re * re + im * im;
                res[c] = fminf(mag * inv[r][c], 1.0f);
            }
            *(float4*)(ob + (size_t)r * 256) =
                make_float4(res[0], res[1], res[2], res[3]);
        }
        ob += 65536;
    }
}

extern "C" void kernel_launch(void* const* d_in, const int* in_sizes, int n_in,
                              void* d_out, int out_size) {
    const float* x = (const float*)d_in[0];        // (32,1,256,256) fp32
    const float* w = (const float*)d_in[1];        // (2,4,3) fp32
    float* out = (float*)d_out;                    // (32,16,256,256) fp32

    dim3 block(64, 4, 1);
    dim3 grid(1, 32, 32);
    qconv_kernel<<<grid, block>>>(x, w, out);
}